// round 3
// baseline (speedup 1.0000x reference)
#include <cuda_runtime.h>
#include <cuda_bf16.h>
#include <stdint.h>

#define BB 8
#define NN 4096
#define NEG_SLOPE 0.01f

// GEMM: M=512 ((b,f) rows), N=4096 (i), K=4096 (j). CTA tile 128x128, K chunk 64.
#define STAGE_BYTES 49152          // Ahi 16KB + Alo 16KB + B 16KB
#define NSTAGE 3
#define SMEM_DYN (NSTAGE * STAGE_BYTES)

// -------- scratch (device globals; no allocation allowed) --------
__device__ __nv_bfloat16 g_maskT[(size_t)NN * NN];        // maskT[i][j]
__device__ __nv_bfloat16 g_hT_hi[(size_t)BB * 64 * NN];   // hT[b][f][n], row (b*64+f)
__device__ __nv_bfloat16 g_hT_lo[(size_t)BB * 64 * NN];
__device__ float g_s1[BB * NN];
__device__ float g_s2[BB * NN];
__device__ __align__(16) float g_hsum[BB * 64];

// -------- helpers --------
__device__ __forceinline__ uint32_t smem_u32(const void* p) {
    uint32_t a;
    asm("{ .reg .u64 t; cvta.to.shared.u64 t, %1; cvt.u32.u64 %0, t; }" : "=r"(a) : "l"(p));
    return a;
}
#define SW128(x) ((x) ^ (((x) >> 3) & 0x70))
__device__ __forceinline__ void cp16(uint32_t s, const void* g) {
    asm volatile("cp.async.cg.shared.global [%0], [%1], 16;" :: "r"(s), "l"(g) : "memory");
}
#define CP_COMMIT() asm volatile("cp.async.commit_group;" ::: "memory")

__device__ __forceinline__ void mma_bf16(float* c, const uint32_t* A, const uint32_t* B) {
    asm volatile(
        "mma.sync.aligned.m16n8k16.row.col.f32.bf16.bf16.f32 "
        "{%0,%1,%2,%3}, {%4,%5,%6,%7}, {%8,%9}, {%0,%1,%2,%3};"
        : "+f"(c[0]), "+f"(c[1]), "+f"(c[2]), "+f"(c[3])
        : "r"(A[0]), "r"(A[1]), "r"(A[2]), "r"(A[3]), "r"(B[0]), "r"(B[1]));
}
__device__ __forceinline__ uint32_t lds32(uint32_t addr) {
    uint32_t v;
    asm volatile("ld.shared.b32 %0, [%1];" : "=r"(v) : "r"(addr));
    return v;
}

// -------- kernel 1: maskT[i][j] = (adj[j+1][i] > 0), j==N-1 -> 0 --------
__global__ void k_mask_transpose(const int* __restrict__ adj) {
    __shared__ float tile[32][33];
    int i0 = blockIdx.x * 32, j0 = blockIdx.y * 32;
    int tx = threadIdx.x, ty = threadIdx.y;  // 32 x 8
#pragma unroll
    for (int r = 0; r < 4; r++) {
        int jl = ty + r * 8, j = j0 + jl;
        float v = 0.f;
        if (j + 1 < NN) v = (adj[(size_t)(j + 1) * NN + (i0 + tx)] > 0) ? 1.f : 0.f;
        tile[jl][tx] = v;
    }
    __syncthreads();
#pragma unroll
    for (int r = 0; r < 4; r++) {
        int il = ty + r * 8;
        g_maskT[(size_t)(i0 + il) * NN + (j0 + tx)] = __float2bfloat16(tile[tx][il]);
    }
}

// -------- kernel 2: h = inp@W^T + b (row 0 zeroed); hi/lo split + s1 --------
__global__ void __launch_bounds__(256) k_compute_h(const float* __restrict__ inp,
                                                   const float* __restrict__ W_w,
                                                   const float* __restrict__ W_b,
                                                   const float* __restrict__ a) {
    __shared__ __align__(16) float Wsh[64 * 64];
    __shared__ float bsh[64];
    int tid = threadIdx.x, b = blockIdx.y;
    int n = blockIdx.x * 256 + tid;
    for (int i = tid; i < 64 * 64; i += 256) Wsh[i] = W_w[i];
    if (tid < 64) bsh[tid] = W_b[tid];
    __syncthreads();

    float x[64];
    const float4* src = reinterpret_cast<const float4*>(inp + ((size_t)b * NN + n) * 64);
#pragma unroll
    for (int q = 0; q < 16; q++) {
        float4 v = src[q];
        x[4 * q] = v.x; x[4 * q + 1] = v.y; x[4 * q + 2] = v.z; x[4 * q + 3] = v.w;
    }
    float s1 = 0.f;
    for (int f = 0; f < 64; f++) {
        float acc = bsh[f];
        const float4* wr = reinterpret_cast<const float4*>(Wsh + f * 64);
#pragma unroll
        for (int q = 0; q < 16; q++) {
            float4 w4 = wr[q];
            acc = fmaf(x[4 * q], w4.x, acc);
            acc = fmaf(x[4 * q + 1], w4.y, acc);
            acc = fmaf(x[4 * q + 2], w4.z, acc);
            acc = fmaf(x[4 * q + 3], w4.w, acc);
        }
        if (n == 0) acc = 0.f;
        __nv_bfloat16 hi = __float2bfloat16(acc);
        float lo = acc - __bfloat162float(hi);
        size_t o = ((size_t)b * 64 + f) * NN + n;
        g_hT_hi[o] = hi;
        g_hT_lo[o] = __float2bfloat16(lo);
        s1 = fmaf(acc, a[(size_t)f * NN + n], s1);
    }
    g_s1[b * NN + n] = s1;
}

// -------- kernel 3: hsum[b][f] = sum_n (hi+lo), deterministic --------
__global__ void k_hsum() {
    __shared__ float red[256];
    int b = blockIdx.y, f = blockIdx.x, tid = threadIdx.x;
    const __nv_bfloat16* hi = g_hT_hi + ((size_t)b * 64 + f) * NN;
    const __nv_bfloat16* lo = g_hT_lo + ((size_t)b * 64 + f) * NN;
    float s = 0.f;
    for (int n = tid; n < NN; n += 256)
        s += __bfloat162float(hi[n]) + __bfloat162float(lo[n]);
    red[tid] = s;
    __syncthreads();
    for (int st = 128; st > 0; st >>= 1) {
        if (tid < st) red[tid] += red[tid + st];
        __syncthreads();
    }
    if (tid == 0) g_hsum[b * 64 + f] = red[0];
}

// -------- kernel 4: big GEMM (mma.sync bf16 hi/lo) + s2 epilogue --------
__device__ __forceinline__ void load_chunk(uint32_t stage, const char* Ahi, const char* Alo,
                                           const char* Bm, int c, int tid) {
    size_t koff = (size_t)c * 128;  // 64 bf16 = 128B per row
#pragma unroll
    for (int p = 0; p < 4; p++) {
        int q = tid + p * 256;                 // 0..1023 = 128 rows x 8 chunks
        int row = q >> 3, cb = (q & 7) * 16;
        uint32_t soff = SW128((uint32_t)(row * 128 + cb));
        size_t goff = (size_t)row * 8192 + koff + cb;
        cp16(stage + soff, Ahi + goff);
        cp16(stage + 16384 + soff, Alo + goff);
        cp16(stage + 32768 + soff, Bm + goff);
    }
}

__global__ void __launch_bounds__(256) k_gemm(const float* __restrict__ a) {
    extern __shared__ char smem[];
    uint32_t sb = smem_u32(smem);
    int tid = threadIdx.x, lane = tid & 31, wid = tid >> 5;
    int wm = wid & 3, wn = wid >> 2;          // warp tile: rows wm*32, cols wn*64
    int mtile = blockIdx.x, i0 = blockIdx.y * 128;

    const char* Ahi = (const char*)g_hT_hi + (size_t)mtile * 128 * 8192;
    const char* Alo = (const char*)g_hT_lo + (size_t)mtile * 128 * 8192;
    const char* Bm  = (const char*)g_maskT + (size_t)i0 * 8192;

    float acc[2][8][4];
#pragma unroll
    for (int mt = 0; mt < 2; mt++)
#pragma unroll
        for (int nt = 0; nt < 8; nt++)
#pragma unroll
            for (int r = 0; r < 4; r++) acc[mt][nt][r] = 0.f;

    int tig = lane & 3, grp = lane >> 2;
    int ar = wm * 32 + grp;                    // A row (f side); +8/+16 same mod-8
    uint32_t acx = (uint32_t)((ar & 7) << 4);  // swizzle constant
    uint32_t a_base = sb + (uint32_t)ar * 128;
    int br = wn * 64 + grp;                    // B row (n side)
    uint32_t bcx = (uint32_t)((br & 7) << 4);
    uint32_t b_base = sb + 32768u + (uint32_t)br * 128;
    uint32_t q4 = (uint32_t)(tig * 4);

    for (int c = 0; c < NSTAGE; c++) {
        load_chunk(sb + (uint32_t)c * STAGE_BYTES, Ahi, Alo, Bm, c, tid);
        CP_COMMIT();
    }
    for (int c = 0; c < 64; c++) {
        asm volatile("cp.async.wait_group 2;" ::: "memory");
        __syncthreads();
        uint32_t soff = (uint32_t)(c % NSTAGE) * STAGE_BYTES;
#pragma unroll
        for (int ks = 0; ks < 4; ks++) {
            uint32_t k0 = (uint32_t)ks * 32 + q4;
            uint32_t oA0 = (k0 ^ acx), oA1 = ((k0 + 16) ^ acx);
            uint32_t oB0 = (k0 ^ bcx), oB1 = ((k0 + 16) ^ bcx);
            uint32_t bfr[8][2];
#pragma unroll
            for (int nt = 0; nt < 8; nt++) {
                uint32_t ad = b_base + soff + (uint32_t)nt * 1024;
                bfr[nt][0] = lds32(ad + oB0);
                bfr[nt][1] = lds32(ad + oB1);
            }
#pragma unroll
            for (int mt = 0; mt < 2; mt++) {
                uint32_t ra = a_base + soff + (uint32_t)mt * 2048;
                uint32_t ah[4], al[4];
                ah[0] = lds32(ra + oA0);
                ah[1] = lds32(ra + 1024 + oA0);
                ah[2] = lds32(ra + oA1);
                ah[3] = lds32(ra + 1024 + oA1);
                al[0] = lds32(ra + 16384 + oA0);
                al[1] = lds32(ra + 16384 + 1024 + oA0);
                al[2] = lds32(ra + 16384 + oA1);
                al[3] = lds32(ra + 16384 + 1024 + oA1);
#pragma unroll
                for (int nt = 0; nt < 8; nt++) {
                    mma_bf16(acc[mt][nt], ah, bfr[nt]);
                    mma_bf16(acc[mt][nt], al, bfr[nt]);
                }
            }
        }
        __syncthreads();
        int cn = c + NSTAGE;
        if (cn < 64)
            load_chunk(sb + (uint32_t)(cn % NSTAGE) * STAGE_BYTES, Ahi, Alo, Bm, cn, tid);
        CP_COMMIT();
    }

    // epilogue: s2[b][i] = sum_f C[(b,f)][i] * a2[f][i]
    float* a2s = (float*)smem;                        // [64][129]
    float* part = (float*)(smem + 64 * 129 * 4);      // [8 warps][64]
    for (int idx = tid; idx < 64 * 128; idx += 256) {
        int f = idx >> 7, cc = idx & 127;
        a2s[f * 129 + cc] = a[(size_t)(64 + f) * NN + i0 + cc];
    }
    __syncthreads();

    float p[8][2];
#pragma unroll
    for (int nt = 0; nt < 8; nt++) { p[nt][0] = 0.f; p[nt][1] = 0.f; }
#pragma unroll
    for (int mt = 0; mt < 2; mt++) {
        int f0 = (wm * 32 + mt * 16 + grp) & 63;
        int f1 = (wm * 32 + mt * 16 + grp + 8) & 63;
#pragma unroll
        for (int nt = 0; nt < 8; nt++) {
            int col = wn * 64 + nt * 8 + tig * 2;
            p[nt][0] += acc[mt][nt][0] * a2s[f0 * 129 + col] +
                        acc[mt][nt][2] * a2s[f1 * 129 + col];
            p[nt][1] += acc[mt][nt][1] * a2s[f0 * 129 + col + 1] +
                        acc[mt][nt][3] * a2s[f1 * 129 + col + 1];
        }
    }
#pragma unroll
    for (int off = 16; off >= 4; off >>= 1)
#pragma unroll
        for (int nt = 0; nt < 8; nt++) {
            p[nt][0] += __shfl_xor_sync(0xFFFFFFFFu, p[nt][0], off);
            p[nt][1] += __shfl_xor_sync(0xFFFFFFFFu, p[nt][1], off);
        }
    if (lane < 4) {
#pragma unroll
        for (int nt = 0; nt < 8; nt++) {
            part[wid * 64 + nt * 8 + tig * 2]     = p[nt][0];
            part[wid * 64 + nt * 8 + tig * 2 + 1] = p[nt][1];
        }
    }
    __syncthreads();
    {
        int bloc = tid >> 7, col = tid & 127;
        int wnn = col >> 6, c64 = col & 63;
        int w0 = wnn * 4 + bloc * 2;   // warps covering this (batch, col-block)
        float v = part[w0 * 64 + c64] + part[(w0 + 1) * 64 + c64];
        g_s2[(size_t)(mtile * 2 + bloc) * NN + i0 + col] = v;
    }
}

// -------- kernel 5: out[b,n,f] = leaky(s[b,n] * hsum[b,f]) --------
__global__ void __launch_bounds__(256) k_out(float* __restrict__ out) {
    __shared__ __align__(16) float hs[64];
    int b = blockIdx.y, n0 = blockIdx.x * 16, tid = threadIdx.x;
    if (tid < 64) hs[tid] = g_hsum[b * 64 + tid];
    __syncthreads();
    int r = tid >> 4, q = tid & 15;
    int n = n0 + r;
    float s = (n == 0) ? 0.f : (g_s1[b * NN + n] + g_s2[b * NN + n]);
    float4 h4 = reinterpret_cast<const float4*>(hs)[q];
    float4 v;
    v.x = s * h4.x; v.y = s * h4.y; v.z = s * h4.z; v.w = s * h4.w;
    v.x = v.x >= 0.f ? v.x : NEG_SLOPE * v.x;
    v.y = v.y >= 0.f ? v.y : NEG_SLOPE * v.y;
    v.z = v.z >= 0.f ? v.z : NEG_SLOPE * v.z;
    v.w = v.w >= 0.f ? v.w : NEG_SLOPE * v.w;
    reinterpret_cast<float4*>(out + ((size_t)b * NN + n) * 64)[q] = v;
}

extern "C" void kernel_launch(void* const* d_in, const int* in_sizes, int n_in,
                              void* d_out, int out_size) {
    const float* inp = (const float*)d_in[0];
    const int*   adj = (const int*)d_in[1];
    const float* W_w = (const float*)d_in[2];
    const float* W_b = (const float*)d_in[3];
    const float* a   = (const float*)d_in[4];
    float* out = (float*)d_out;
    cudaFuncSetAttribute(k_gemm, cudaFuncAttributeMaxDynamicSharedMemorySize, SMEM_DYN);
    k_mask_transpose<<<dim3(128, 128), dim3(32, 8)>>>(adj);
    k_compute_h<<<dim3(16, 8), 256>>>(inp, W_w, W_b, a);
    k_hsum<<<dim3(64, 8), 256>>>();
    k_gemm<<<dim3(4, 32), 256, SMEM_DYN>>>(a);
    k_out<<<dim3(256, 8), 256>>>(out);
}

// round 4
// speedup vs baseline: 1.0304x; 1.0304x over previous
#include <cuda_runtime.h>
#include <cuda_bf16.h>
#include <stdint.h>

#define BB 8
#define NN 4096
#define NEG_SLOPE 0.01f

// GEMM: M=512 ((b,f) rows), N=4096 (i), K=4096 (j).
// CTA tile 128x128, K chunk 64, K-split 2 (each CTA does K=2048).
#define STAGE_BYTES 49152          // Ahi 16KB + Alo 16KB + B 16KB
#define NSTAGE 2
#define SMEM_DYN (NSTAGE * STAGE_BYTES)   // 96KB -> 2 CTAs/SM

// -------- scratch (device globals; no allocation allowed) --------
__device__ __nv_bfloat16 g_maskT[(size_t)NN * NN];        // maskT[i][j]
__device__ __nv_bfloat16 g_hT_hi[(size_t)BB * 64 * NN];   // hT[b][f][n], row (b*64+f)
__device__ __nv_bfloat16 g_hT_lo[(size_t)BB * 64 * NN];
__device__ float g_s1[BB * NN];
__device__ float g_s2p[2][BB * NN];                       // per-K-slice partials
__device__ __align__(16) float g_hsum[BB * 64];

// -------- helpers --------
__device__ __forceinline__ uint32_t smem_u32(const void* p) {
    uint32_t a;
    asm("{ .reg .u64 t; cvta.to.shared.u64 t, %1; cvt.u32.u64 %0, t; }" : "=r"(a) : "l"(p));
    return a;
}
#define SW128(x) ((x) ^ (((x) >> 3) & 0x70))
__device__ __forceinline__ void cp16(uint32_t s, const void* g) {
    asm volatile("cp.async.cg.shared.global [%0], [%1], 16;" :: "r"(s), "l"(g) : "memory");
}
#define CP_COMMIT() asm volatile("cp.async.commit_group;" ::: "memory")

__device__ __forceinline__ void mma_bf16(float* c, const uint32_t* A, const uint32_t* B) {
    asm volatile(
        "mma.sync.aligned.m16n8k16.row.col.f32.bf16.bf16.f32 "
        "{%0,%1,%2,%3}, {%4,%5,%6,%7}, {%8,%9}, {%0,%1,%2,%3};"
        : "+f"(c[0]), "+f"(c[1]), "+f"(c[2]), "+f"(c[3])
        : "r"(A[0]), "r"(A[1]), "r"(A[2]), "r"(A[3]), "r"(B[0]), "r"(B[1]));
}
__device__ __forceinline__ uint32_t lds32(uint32_t addr) {
    uint32_t v;
    asm volatile("ld.shared.b32 %0, [%1];" : "=r"(v) : "r"(addr));
    return v;
}

// -------- kernel 1: maskT[i][j] = (adj[j+1][i] > 0), j==N-1 -> 0 --------
__global__ void k_mask_transpose(const int* __restrict__ adj) {
    __shared__ float tile[32][33];
    int i0 = blockIdx.x * 32, j0 = blockIdx.y * 32;
    int tx = threadIdx.x, ty = threadIdx.y;  // 32 x 8
#pragma unroll
    for (int r = 0; r < 4; r++) {
        int jl = ty + r * 8, j = j0 + jl;
        float v = 0.f;
        if (j + 1 < NN) v = (adj[(size_t)(j + 1) * NN + (i0 + tx)] > 0) ? 1.f : 0.f;
        tile[jl][tx] = v;
    }
    __syncthreads();
#pragma unroll
    for (int r = 0; r < 4; r++) {
        int il = ty + r * 8;
        g_maskT[(size_t)(i0 + il) * NN + (j0 + tx)] = __float2bfloat16(tile[tx][il]);
    }
}

// -------- kernel 2: h = inp@W^T + b (row 0 zeroed); hi/lo split + s1 --------
__global__ void __launch_bounds__(256) k_compute_h(const float* __restrict__ inp,
                                                   const float* __restrict__ W_w,
                                                   const float* __restrict__ W_b,
                                                   const float* __restrict__ a) {
    __shared__ __align__(16) float Wsh[64 * 64];
    __shared__ float bsh[64];
    int tid = threadIdx.x, b = blockIdx.y;
    int n = blockIdx.x * 256 + tid;
    for (int i = tid; i < 64 * 64; i += 256) Wsh[i] = W_w[i];
    if (tid < 64) bsh[tid] = W_b[tid];
    __syncthreads();

    float x[64];
    const float4* src = reinterpret_cast<const float4*>(inp + ((size_t)b * NN + n) * 64);
#pragma unroll
    for (int q = 0; q < 16; q++) {
        float4 v = src[q];
        x[4 * q] = v.x; x[4 * q + 1] = v.y; x[4 * q + 2] = v.z; x[4 * q + 3] = v.w;
    }
    float s1 = 0.f;
    for (int f = 0; f < 64; f++) {
        float acc = bsh[f];
        const float4* wr = reinterpret_cast<const float4*>(Wsh + f * 64);
#pragma unroll
        for (int q = 0; q < 16; q++) {
            float4 w4 = wr[q];
            acc = fmaf(x[4 * q], w4.x, acc);
            acc = fmaf(x[4 * q + 1], w4.y, acc);
            acc = fmaf(x[4 * q + 2], w4.z, acc);
            acc = fmaf(x[4 * q + 3], w4.w, acc);
        }
        if (n == 0) acc = 0.f;
        __nv_bfloat16 hi = __float2bfloat16(acc);
        float lo = acc - __bfloat162float(hi);
        size_t o = ((size_t)b * 64 + f) * NN + n;
        g_hT_hi[o] = hi;
        g_hT_lo[o] = __float2bfloat16(lo);
        s1 = fmaf(acc, a[(size_t)f * NN + n], s1);
    }
    g_s1[b * NN + n] = s1;
}

// -------- kernel 3: hsum[b][f] = sum_n (hi+lo), deterministic --------
__global__ void k_hsum() {
    __shared__ float red[256];
    int b = blockIdx.y, f = blockIdx.x, tid = threadIdx.x;
    const __nv_bfloat16* hi = g_hT_hi + ((size_t)b * 64 + f) * NN;
    const __nv_bfloat16* lo = g_hT_lo + ((size_t)b * 64 + f) * NN;
    float s = 0.f;
    for (int n = tid; n < NN; n += 256)
        s += __bfloat162float(hi[n]) + __bfloat162float(lo[n]);
    red[tid] = s;
    __syncthreads();
    for (int st = 128; st > 0; st >>= 1) {
        if (tid < st) red[tid] += red[tid + st];
        __syncthreads();
    }
    if (tid == 0) g_hsum[b * 64 + f] = red[0];
}

// -------- kernel 4: big GEMM (mma.sync bf16 hi/lo) + s2 epilogue --------
__device__ __forceinline__ void load_chunk(uint32_t stage, const char* Ahi, const char* Alo,
                                           const char* Bm, int c, int tid) {
    size_t koff = (size_t)c * 128;  // 64 bf16 = 128B per row
#pragma unroll
    for (int p = 0; p < 4; p++) {
        int q = tid + p * 256;                 // 0..1023 = 128 rows x 8 chunks
        int row = q >> 3, cb = (q & 7) * 16;
        uint32_t soff = SW128((uint32_t)(row * 128 + cb));
        size_t goff = (size_t)row * 8192 + koff + cb;
        cp16(stage + soff, Ahi + goff);
        cp16(stage + 16384 + soff, Alo + goff);
        cp16(stage + 32768 + soff, Bm + goff);
    }
}

__global__ void __launch_bounds__(256, 2) k_gemm(const float* __restrict__ a) {
    extern __shared__ char smem[];
    uint32_t sb = smem_u32(smem);
    int tid = threadIdx.x, lane = tid & 31, wid = tid >> 5;
    int wm = wid & 3, wn = wid >> 2;          // warp tile: rows wm*32, cols wn*64
    int mtile = blockIdx.x, i0 = blockIdx.y * 128;
    int kslice = blockIdx.z, c0 = kslice * 32;  // 32 chunks of 64 per slice

    const char* Ahi = (const char*)g_hT_hi + (size_t)mtile * 128 * 8192;
    const char* Alo = (const char*)g_hT_lo + (size_t)mtile * 128 * 8192;
    const char* Bm  = (const char*)g_maskT + (size_t)i0 * 8192;

    float acc[2][8][4];
#pragma unroll
    for (int mt = 0; mt < 2; mt++)
#pragma unroll
        for (int nt = 0; nt < 8; nt++)
#pragma unroll
            for (int r = 0; r < 4; r++) acc[mt][nt][r] = 0.f;

    int tig = lane & 3, grp = lane >> 2;
    int ar = wm * 32 + grp;                    // A row (f side); +8/+16 same mod-8
    uint32_t acx = (uint32_t)((ar & 7) << 4);  // swizzle constant
    uint32_t a_base = sb + (uint32_t)ar * 128;
    int br = wn * 64 + grp;                    // B row (n side)
    uint32_t bcx = (uint32_t)((br & 7) << 4);
    uint32_t b_base = sb + 32768u + (uint32_t)br * 128;
    uint32_t q4 = (uint32_t)(tig * 4);

    for (int c = 0; c < NSTAGE; c++) {
        load_chunk(sb + (uint32_t)c * STAGE_BYTES, Ahi, Alo, Bm, c0 + c, tid);
        CP_COMMIT();
    }
    for (int c = 0; c < 32; c++) {
        asm volatile("cp.async.wait_group 1;" ::: "memory");
        __syncthreads();
        uint32_t soff = (uint32_t)(c & 1) * STAGE_BYTES;
#pragma unroll
        for (int ks = 0; ks < 4; ks++) {
            uint32_t k0 = (uint32_t)ks * 32 + q4;
            uint32_t oA0 = (k0 ^ acx), oA1 = ((k0 + 16) ^ acx);
            uint32_t oB0 = (k0 ^ bcx), oB1 = ((k0 + 16) ^ bcx);
            uint32_t bfr[8][2];
#pragma unroll
            for (int nt = 0; nt < 8; nt++) {
                uint32_t ad = b_base + soff + (uint32_t)nt * 1024;
                bfr[nt][0] = lds32(ad + oB0);
                bfr[nt][1] = lds32(ad + oB1);
            }
#pragma unroll
            for (int mt = 0; mt < 2; mt++) {
                uint32_t ra = a_base + soff + (uint32_t)mt * 2048;
                uint32_t ah[4], al[4];
                ah[0] = lds32(ra + oA0);
                ah[1] = lds32(ra + 1024 + oA0);
                ah[2] = lds32(ra + oA1);
                ah[3] = lds32(ra + 1024 + oA1);
                al[0] = lds32(ra + 16384 + oA0);
                al[1] = lds32(ra + 16384 + 1024 + oA0);
                al[2] = lds32(ra + 16384 + oA1);
                al[3] = lds32(ra + 16384 + 1024 + oA1);
#pragma unroll
                for (int nt = 0; nt < 8; nt++) {
                    mma_bf16(acc[mt][nt], ah, bfr[nt]);
                    mma_bf16(acc[mt][nt], al, bfr[nt]);
                }
            }
        }
        __syncthreads();
        int cn = c + NSTAGE;
        if (cn < 32)
            load_chunk(sb + (uint32_t)(cn & 1) * STAGE_BYTES, Ahi, Alo, Bm, c0 + cn, tid);
        CP_COMMIT();
    }

    // epilogue: s2p[kslice][b][i] = sum_f C[(b,f)][i] * a2[f][i]
    float* a2s = (float*)smem;                        // [64][129]
    float* part = (float*)(smem + 64 * 129 * 4);      // [8 warps][64]
    for (int idx = tid; idx < 64 * 128; idx += 256) {
        int f = idx >> 7, cc = idx & 127;
        a2s[f * 129 + cc] = a[(size_t)(64 + f) * NN + i0 + cc];
    }
    __syncthreads();

    float p[8][2];
#pragma unroll
    for (int nt = 0; nt < 8; nt++) { p[nt][0] = 0.f; p[nt][1] = 0.f; }
#pragma unroll
    for (int mt = 0; mt < 2; mt++) {
        int f0 = (wm * 32 + mt * 16 + grp) & 63;
        int f1 = (wm * 32 + mt * 16 + grp + 8) & 63;
#pragma unroll
        for (int nt = 0; nt < 8; nt++) {
            int col = wn * 64 + nt * 8 + tig * 2;
            p[nt][0] += acc[mt][nt][0] * a2s[f0 * 129 + col] +
                        acc[mt][nt][2] * a2s[f1 * 129 + col];
            p[nt][1] += acc[mt][nt][1] * a2s[f0 * 129 + col + 1] +
                        acc[mt][nt][3] * a2s[f1 * 129 + col + 1];
        }
    }
#pragma unroll
    for (int off = 16; off >= 4; off >>= 1)
#pragma unroll
        for (int nt = 0; nt < 8; nt++) {
            p[nt][0] += __shfl_xor_sync(0xFFFFFFFFu, p[nt][0], off);
            p[nt][1] += __shfl_xor_sync(0xFFFFFFFFu, p[nt][1], off);
        }
    if (lane < 4) {
#pragma unroll
        for (int nt = 0; nt < 8; nt++) {
            part[wid * 64 + nt * 8 + tig * 2]     = p[nt][0];
            part[wid * 64 + nt * 8 + tig * 2 + 1] = p[nt][1];
        }
    }
    __syncthreads();
    {
        int bloc = tid >> 7, col = tid & 127;
        int wnn = col >> 6, c64 = col & 63;
        int w0 = wnn * 4 + bloc * 2;   // warps covering this (batch, col-block)
        float v = part[w0 * 64 + c64] + part[(w0 + 1) * 64 + c64];
        g_s2p[kslice][(size_t)(mtile * 2 + bloc) * NN + i0 + col] = v;
    }
}

// -------- kernel 5: out[b,n,f] = leaky(s[b,n] * hsum[b,f]) --------
__global__ void __launch_bounds__(256) k_out(float* __restrict__ out) {
    __shared__ __align__(16) float hs[64];
    int b = blockIdx.y, n0 = blockIdx.x * 16, tid = threadIdx.x;
    if (tid < 64) hs[tid] = g_hsum[b * 64 + tid];
    __syncthreads();
    int r = tid >> 4, q = tid & 15;
    int n = n0 + r;
    float s = (n == 0) ? 0.f
                       : (g_s1[b * NN + n] + g_s2p[0][b * NN + n] + g_s2p[1][b * NN + n]);
    float4 h4 = reinterpret_cast<const float4*>(hs)[q];
    float4 v;
    v.x = s * h4.x; v.y = s * h4.y; v.z = s * h4.z; v.w = s * h4.w;
    v.x = v.x >= 0.f ? v.x : NEG_SLOPE * v.x;
    v.y = v.y >= 0.f ? v.y : NEG_SLOPE * v.y;
    v.z = v.z >= 0.f ? v.z : NEG_SLOPE * v.z;
    v.w = v.w >= 0.f ? v.w : NEG_SLOPE * v.w;
    reinterpret_cast<float4*>(out + ((size_t)b * NN + n) * 64)[q] = v;
}

extern "C" void kernel_launch(void* const* d_in, const int* in_sizes, int n_in,
                              void* d_out, int out_size) {
    const float* inp = (const float*)d_in[0];
    const int*   adj = (const int*)d_in[1];
    const float* W_w = (const float*)d_in[2];
    const float* W_b = (const float*)d_in[3];
    const float* a   = (const float*)d_in[4];
    float* out = (float*)d_out;
    cudaFuncSetAttribute(k_gemm, cudaFuncAttributeMaxDynamicSharedMemorySize, SMEM_DYN);
    k_mask_transpose<<<dim3(128, 128), dim3(32, 8)>>>(adj);
    k_compute_h<<<dim3(16, 8), 256>>>(inp, W_w, W_b, a);
    k_hsum<<<dim3(64, 8), 256>>>();
    k_gemm<<<dim3(4, 32, 2), 256, SMEM_DYN>>>(a);
    k_out<<<dim3(256, 8), 256>>>(out);
}

// round 5
// speedup vs baseline: 1.0869x; 1.0548x over previous
#include <cuda_runtime.h>
#include <cuda_bf16.h>
#include <stdint.h>

#define BB 8
#define NN 4096
#define NEG_SLOPE 0.01f

// GEMM: M=512 ((b,f) rows), N=4096 (i), K=4096 (j).
// CTA tile 128x128, K chunk 64, K-split 2 (each CTA does K=2048).
#define STAGE_BYTES 49152          // Ahi 16KB + Alo 16KB + B 16KB
#define NSTAGE 2
#define SMEM_DYN (NSTAGE * STAGE_BYTES)   // 96KB -> 2 CTAs/SM

// -------- scratch (device globals; no allocation allowed) --------
__device__ __nv_bfloat16 g_maskT[(size_t)NN * NN];        // maskT[i][j]
__device__ __nv_bfloat16 g_hT_hi[(size_t)BB * 64 * NN];   // hT[b][f][n], row (b*64+f)
__device__ __nv_bfloat16 g_hT_lo[(size_t)BB * 64 * NN];
__device__ float g_s1[BB * NN];
__device__ float g_s2p[2][BB * NN];                       // per-K-slice partials
__device__ float g_hsumP[16][BB][64];                     // per-block partials
__device__ __align__(16) float g_hsum[BB * 64];

// -------- helpers --------
__device__ __forceinline__ uint32_t smem_u32(const void* p) {
    uint32_t a;
    asm("{ .reg .u64 t; cvta.to.shared.u64 t, %1; cvt.u32.u64 %0, t; }" : "=r"(a) : "l"(p));
    return a;
}
#define SW128(x) ((x) ^ (((x) >> 3) & 0x70))
__device__ __forceinline__ void cp16(uint32_t s, const void* g) {
    asm volatile("cp.async.cg.shared.global [%0], [%1], 16;" :: "r"(s), "l"(g) : "memory");
}
#define CP_COMMIT() asm volatile("cp.async.commit_group;" ::: "memory")

__device__ __forceinline__ void mma_bf16(float* c, const uint32_t* A, const uint32_t* B) {
    asm volatile(
        "mma.sync.aligned.m16n8k16.row.col.f32.bf16.bf16.f32 "
        "{%0,%1,%2,%3}, {%4,%5,%6,%7}, {%8,%9}, {%0,%1,%2,%3};"
        : "+f"(c[0]), "+f"(c[1]), "+f"(c[2]), "+f"(c[3])
        : "r"(A[0]), "r"(A[1]), "r"(A[2]), "r"(A[3]), "r"(B[0]), "r"(B[1]));
}
#define LDSM4(r0, r1, r2, r3, addr) \
    asm volatile("ldmatrix.sync.aligned.m8n8.x4.shared.b16 {%0,%1,%2,%3}, [%4];" \
                 : "=r"(r0), "=r"(r1), "=r"(r2), "=r"(r3) : "r"(addr))

// -------- kernel 1: maskT[i][j] = (adj[j+1][i] > 0), j==N-1 -> 0 --------
__global__ void k_mask_transpose(const int* __restrict__ adj) {
    __shared__ float tile[32][33];
    int i0 = blockIdx.x * 32, j0 = blockIdx.y * 32;
    int tx = threadIdx.x, ty = threadIdx.y;  // 32 x 8
#pragma unroll
    for (int r = 0; r < 4; r++) {
        int jl = ty + r * 8, j = j0 + jl;
        float v = 0.f;
        if (j + 1 < NN) v = (adj[(size_t)(j + 1) * NN + (i0 + tx)] > 0) ? 1.f : 0.f;
        tile[jl][tx] = v;
    }
    __syncthreads();
#pragma unroll
    for (int r = 0; r < 4; r++) {
        int il = ty + r * 8;
        g_maskT[(size_t)(i0 + il) * NN + (j0 + tx)] = __float2bfloat16(tile[tx][il]);
    }
}

// -------- kernel 2: h = inp@W^T + b (row 0 zeroed); hi/lo split + s1 + hsum partials --------
__global__ void __launch_bounds__(256) k_compute_h(const float* __restrict__ inp,
                                                   const float* __restrict__ W_w,
                                                   const float* __restrict__ W_b,
                                                   const float* __restrict__ a) {
    __shared__ __align__(16) float Wsh[64 * 64];
    __shared__ float bsh[64];
    __shared__ float wred[8][64];
    int tid = threadIdx.x, lane = tid & 31, wid = tid >> 5, b = blockIdx.y;
    int n = blockIdx.x * 256 + tid;
    for (int i = tid; i < 64 * 64; i += 256) Wsh[i] = W_w[i];
    if (tid < 64) bsh[tid] = W_b[tid];
    __syncthreads();

    float x[64];
    const float4* src = reinterpret_cast<const float4*>(inp + ((size_t)b * NN + n) * 64);
#pragma unroll
    for (int q = 0; q < 16; q++) {
        float4 v = src[q];
        x[4 * q] = v.x; x[4 * q + 1] = v.y; x[4 * q + 2] = v.z; x[4 * q + 3] = v.w;
    }
    float s1 = 0.f;
    for (int f = 0; f < 64; f++) {
        float acc = bsh[f];
        const float4* wr = reinterpret_cast<const float4*>(Wsh + f * 64);
#pragma unroll
        for (int q = 0; q < 16; q++) {
            float4 w4 = wr[q];
            acc = fmaf(x[4 * q], w4.x, acc);
            acc = fmaf(x[4 * q + 1], w4.y, acc);
            acc = fmaf(x[4 * q + 2], w4.z, acc);
            acc = fmaf(x[4 * q + 3], w4.w, acc);
        }
        if (n == 0) acc = 0.f;
        __nv_bfloat16 hi = __float2bfloat16(acc);
        float lo = acc - __bfloat162float(hi);
        size_t o = ((size_t)b * 64 + f) * NN + n;
        g_hT_hi[o] = hi;
        g_hT_lo[o] = __float2bfloat16(lo);
        s1 = fmaf(acc, a[(size_t)f * NN + n], s1);
        float v = acc;
#pragma unroll
        for (int off = 16; off > 0; off >>= 1)
            v += __shfl_xor_sync(0xFFFFFFFFu, v, off);
        if (lane == 0) wred[wid][f] = v;
    }
    g_s1[b * NN + n] = s1;
    __syncthreads();
    if (tid < 64) {
        float t = 0.f;
#pragma unroll
        for (int w = 0; w < 8; w++) t += wred[w][tid];
        g_hsumP[blockIdx.x][b][tid] = t;
    }
}

// -------- kernel 2b: finish hsum --------
__global__ void k_hsum_final() {
    int b = threadIdx.x >> 6, f = threadIdx.x & 63;   // 512 threads
    float t = 0.f;
#pragma unroll
    for (int p = 0; p < 16; p++) t += g_hsumP[p][b][f];
    g_hsum[b * 64 + f] = t;
}

// -------- kernel 4: big GEMM (mma.sync bf16 hi/lo, LDSM feeds) + s2 epilogue --------
__device__ __forceinline__ void load_chunk(uint32_t stage, const char* Ahi, const char* Alo,
                                           const char* Bm, int c, int tid) {
    size_t koff = (size_t)c * 128;  // 64 bf16 = 128B per row
#pragma unroll
    for (int p = 0; p < 4; p++) {
        int q = tid + p * 256;                 // 0..1023 = 128 rows x 8 chunks
        int row = q >> 3, cb = (q & 7) * 16;
        uint32_t soff = SW128((uint32_t)(row * 128 + cb));
        size_t goff = (size_t)row * 8192 + koff + cb;
        cp16(stage + soff, Ahi + goff);
        cp16(stage + 16384 + soff, Alo + goff);
        cp16(stage + 32768 + soff, Bm + goff);
    }
}

__global__ void __launch_bounds__(256, 2) k_gemm(const float* __restrict__ a) {
    extern __shared__ char smem[];
    uint32_t sb = smem_u32(smem);
    int tid = threadIdx.x, lane = tid & 31, wid = tid >> 5;
    int wm = wid & 3, wn = wid >> 2;          // warp tile: rows wm*32, cols wn*64
    int mtile = blockIdx.x, i0 = blockIdx.y * 128;
    int kslice = blockIdx.z, c0 = kslice * 32;  // 32 chunks of 64 per slice

    const char* Ahi = (const char*)g_hT_hi + (size_t)mtile * 128 * 8192;
    const char* Alo = (const char*)g_hT_lo + (size_t)mtile * 128 * 8192;
    const char* Bm  = (const char*)g_maskT + (size_t)i0 * 8192;

    float acc[2][8][4];
#pragma unroll
    for (int mt = 0; mt < 2; mt++)
#pragma unroll
        for (int nt = 0; nt < 8; nt++)
#pragma unroll
            for (int r = 0; r < 4; r++) acc[mt][nt][r] = 0.f;

    // LDSM per-thread address pieces. Swizzle const shared by A and B:
    uint32_t cx = (uint32_t)((lane & 7) << 4);
    // A: lanes 0-15 -> rows 0-15 (k lo 16B), lanes 16-31 -> rows 0-15 (k hi 16B)
    uint32_t aoff = (uint32_t)(wm * 32 + (lane & 15)) * 128u;
    uint32_t khA = (uint32_t)(((lane >> 4) & 1) << 4);
    // B: lanes 0-15 -> n rows 0-7 (k lo/hi by bit3), lanes 16-31 -> n rows 8-15
    uint32_t boff = 32768u + (uint32_t)(wn * 64 + (lane & 7) + (((lane >> 4) & 1) << 3)) * 128u;
    uint32_t khB = (uint32_t)(((lane >> 3) & 1) << 4);

    for (int c = 0; c < NSTAGE; c++) {
        load_chunk(sb + (uint32_t)c * STAGE_BYTES, Ahi, Alo, Bm, c0 + c, tid);
        CP_COMMIT();
    }
    for (int c = 0; c < 32; c++) {
        asm volatile("cp.async.wait_group 1;" ::: "memory");
        __syncthreads();
        uint32_t so = sb + (uint32_t)(c & 1) * STAGE_BYTES;
#pragma unroll
        for (int ks = 0; ks < 4; ks++) {
            uint32_t kA = ((uint32_t)(ks * 32) + khA) ^ cx;
            uint32_t kB = ((uint32_t)(ks * 32) + khB) ^ cx;
            uint32_t bfr[8][2];
#pragma unroll
            for (int ntp = 0; ntp < 4; ntp++)
                LDSM4(bfr[2 * ntp][0], bfr[2 * ntp][1], bfr[2 * ntp + 1][0], bfr[2 * ntp + 1][1],
                      so + boff + (uint32_t)ntp * 2048 + kB);
            uint32_t ah[2][4], al[2][4];
#pragma unroll
            for (int mt = 0; mt < 2; mt++) {
                uint32_t ra = so + aoff + (uint32_t)mt * 2048 + kA;
                LDSM4(ah[mt][0], ah[mt][1], ah[mt][2], ah[mt][3], ra);
                LDSM4(al[mt][0], al[mt][1], al[mt][2], al[mt][3], ra + 16384);
            }
#pragma unroll
            for (int mt = 0; mt < 2; mt++)
#pragma unroll
                for (int nt = 0; nt < 8; nt++)
                    mma_bf16(acc[mt][nt], ah[mt], bfr[nt]);
#pragma unroll
            for (int mt = 0; mt < 2; mt++)
#pragma unroll
                for (int nt = 0; nt < 8; nt++)
                    mma_bf16(acc[mt][nt], al[mt], bfr[nt]);
        }
        __syncthreads();
        int cn = c + NSTAGE;
        if (cn < 32)
            load_chunk(sb + (uint32_t)(cn & 1) * STAGE_BYTES, Ahi, Alo, Bm, c0 + cn, tid);
        CP_COMMIT();
    }

    // epilogue: s2p[kslice][b][i] = sum_f C[(b,f)][i] * a2[f][i]
    int tig = lane & 3, grp = lane >> 2;
    float* a2s = (float*)smem;                        // [64][129]
    float* part = (float*)(smem + 64 * 129 * 4);      // [8 warps][64]
    for (int idx = tid; idx < 64 * 128; idx += 256) {
        int f = idx >> 7, cc = idx & 127;
        a2s[f * 129 + cc] = a[(size_t)(64 + f) * NN + i0 + cc];
    }
    __syncthreads();

    float p[8][2];
#pragma unroll
    for (int nt = 0; nt < 8; nt++) { p[nt][0] = 0.f; p[nt][1] = 0.f; }
#pragma unroll
    for (int mt = 0; mt < 2; mt++) {
        int f0 = (wm * 32 + mt * 16 + grp) & 63;
        int f1 = (wm * 32 + mt * 16 + grp + 8) & 63;
#pragma unroll
        for (int nt = 0; nt < 8; nt++) {
            int col = wn * 64 + nt * 8 + tig * 2;
            p[nt][0] += acc[mt][nt][0] * a2s[f0 * 129 + col] +
                        acc[mt][nt][2] * a2s[f1 * 129 + col];
            p[nt][1] += acc[mt][nt][1] * a2s[f0 * 129 + col + 1] +
                        acc[mt][nt][3] * a2s[f1 * 129 + col + 1];
        }
    }
#pragma unroll
    for (int off = 16; off >= 4; off >>= 1)
#pragma unroll
        for (int nt = 0; nt < 8; nt++) {
            p[nt][0] += __shfl_xor_sync(0xFFFFFFFFu, p[nt][0], off);
            p[nt][1] += __shfl_xor_sync(0xFFFFFFFFu, p[nt][1], off);
        }
    if (lane < 4) {
#pragma unroll
        for (int nt = 0; nt < 8; nt++) {
            part[wid * 64 + nt * 8 + tig * 2]     = p[nt][0];
            part[wid * 64 + nt * 8 + tig * 2 + 1] = p[nt][1];
        }
    }
    __syncthreads();
    {
        int bloc = tid >> 7, col = tid & 127;
        int wnn = col >> 6, c64 = col & 63;
        int w0 = wnn * 4 + bloc * 2;   // warps covering this (batch, col-block)
        float v = part[w0 * 64 + c64] + part[(w0 + 1) * 64 + c64];
        g_s2p[kslice][(size_t)(mtile * 2 + bloc) * NN + i0 + col] = v;
    }
}

// -------- kernel 5: out[b,n,f] = leaky(s[b,n] * hsum[b,f]) --------
__global__ void __launch_bounds__(256) k_out(float* __restrict__ out) {
    __shared__ __align__(16) float hs[64];
    int b = blockIdx.y, n0 = blockIdx.x * 16, tid = threadIdx.x;
    if (tid < 64) hs[tid] = g_hsum[b * 64 + tid];
    __syncthreads();
    int r = tid >> 4, q = tid & 15;
    int n = n0 + r;
    float s = (n == 0) ? 0.f
                       : (g_s1[b * NN + n] + g_s2p[0][b * NN + n] + g_s2p[1][b * NN + n]);
    float4 h4 = reinterpret_cast<const float4*>(hs)[q];
    float4 v;
    v.x = s * h4.x; v.y = s * h4.y; v.z = s * h4.z; v.w = s * h4.w;
    v.x = v.x >= 0.f ? v.x : NEG_SLOPE * v.x;
    v.y = v.y >= 0.f ? v.y : NEG_SLOPE * v.y;
    v.z = v.z >= 0.f ? v.z : NEG_SLOPE * v.z;
    v.w = v.w >= 0.f ? v.w : NEG_SLOPE * v.w;
    reinterpret_cast<float4*>(out + ((size_t)b * NN + n) * 64)[q] = v;
}

extern "C" void kernel_launch(void* const* d_in, const int* in_sizes, int n_in,
                              void* d_out, int out_size) {
    const float* inp = (const float*)d_in[0];
    const int*   adj = (const int*)d_in[1];
    const float* W_w = (const float*)d_in[2];
    const float* W_b = (const float*)d_in[3];
    const float* a   = (const float*)d_in[4];
    float* out = (float*)d_out;
    cudaFuncSetAttribute(k_gemm, cudaFuncAttributeMaxDynamicSharedMemorySize, SMEM_DYN);
    k_mask_transpose<<<dim3(128, 128), dim3(32, 8)>>>(adj);
    k_compute_h<<<dim3(16, 8), 256>>>(inp, W_w, W_b, a);
    k_hsum_final<<<1, 512>>>();
    k_gemm<<<dim3(4, 32, 2), 256, SMEM_DYN>>>(a);
    k_out<<<dim3(256, 8), 256>>>(out);
}

// round 6
// speedup vs baseline: 1.4225x; 1.3087x over previous
#include <cuda_runtime.h>
#include <cuda_fp16.h>
#include <stdint.h>

#define BB 8
#define NN 4096
#define NEG_SLOPE 0.01f

// GEMM: M=512 ((b,f) rows), N=4096 (i), K=4096 (j), fp16 single pass.
// CTA tile 128x128, K chunk 64, K-split 2 (each CTA does K=2048).
#define STAGE_BYTES 32768          // A 16KB + B 16KB
#define NSTAGE 3
#define SMEM_DYN (NSTAGE * STAGE_BYTES)   // 96KB -> 2 CTAs/SM

// -------- scratch (device globals; no allocation allowed) --------
__device__ __half g_maskT[(size_t)NN * NN];        // maskT[i][j]
__device__ __half g_hT[(size_t)BB * 64 * NN];      // hT[b][f][n], row (b*64+f)
__device__ float g_s1[BB * NN];
__device__ float g_s2p[2][BB * NN];                // per-K-slice partials
__device__ float g_hsumP[16][BB][64];              // per-block partials
__device__ __align__(16) float g_hsum[BB * 64];

// -------- helpers --------
__device__ __forceinline__ uint32_t smem_u32(const void* p) {
    uint32_t a;
    asm("{ .reg .u64 t; cvta.to.shared.u64 t, %1; cvt.u32.u64 %0, t; }" : "=r"(a) : "l"(p));
    return a;
}
#define SW128(x) ((x) ^ (((x) >> 3) & 0x70))
__device__ __forceinline__ void cp16(uint32_t s, const void* g) {
    asm volatile("cp.async.cg.shared.global [%0], [%1], 16;" :: "r"(s), "l"(g) : "memory");
}
#define CP_COMMIT() asm volatile("cp.async.commit_group;" ::: "memory")

__device__ __forceinline__ void mma_f16(float* c, const uint32_t* A, const uint32_t* B) {
    asm volatile(
        "mma.sync.aligned.m16n8k16.row.col.f32.f16.f16.f32 "
        "{%0,%1,%2,%3}, {%4,%5,%6,%7}, {%8,%9}, {%0,%1,%2,%3};"
        : "+f"(c[0]), "+f"(c[1]), "+f"(c[2]), "+f"(c[3])
        : "r"(A[0]), "r"(A[1]), "r"(A[2]), "r"(A[3]), "r"(B[0]), "r"(B[1]));
}
#define LDSM4(r0, r1, r2, r3, addr) \
    asm volatile("ldmatrix.sync.aligned.m8n8.x4.shared.b16 {%0,%1,%2,%3}, [%4];" \
                 : "=r"(r0), "=r"(r1), "=r"(r2), "=r"(r3) : "r"(addr))

// -------- kernel 1: maskT[i][j] = (adj[j+1][i] > 0), j==N-1 -> 0 --------
// 64x64 tile per block, 256 threads. int4 loads, 16B half stores.
__global__ void __launch_bounds__(256) k_mask_transpose(const int* __restrict__ adj) {
    __shared__ __half tile[64][72];
    int tid = threadIdx.x;
    int i0 = blockIdx.x * 64, j0 = blockIdx.y * 64;
    int jl = tid >> 4;            // 0..15
    int il4 = (tid & 15) * 4;     // 0..60
#pragma unroll
    for (int pass = 0; pass < 4; pass++) {
        int j = j0 + jl + pass * 16;
        if (j + 1 < NN) {
            int4 v = *reinterpret_cast<const int4*>(adj + (size_t)(j + 1) * NN + i0 + il4);
            tile[il4 + 0][jl + pass * 16] = __float2half(v.x > 0 ? 1.f : 0.f);
            tile[il4 + 1][jl + pass * 16] = __float2half(v.y > 0 ? 1.f : 0.f);
            tile[il4 + 2][jl + pass * 16] = __float2half(v.z > 0 ? 1.f : 0.f);
            tile[il4 + 3][jl + pass * 16] = __float2half(v.w > 0 ? 1.f : 0.f);
        } else {
            tile[il4 + 0][jl + pass * 16] = __float2half(0.f);
            tile[il4 + 1][jl + pass * 16] = __float2half(0.f);
            tile[il4 + 2][jl + pass * 16] = __float2half(0.f);
            tile[il4 + 3][jl + pass * 16] = __float2half(0.f);
        }
    }
    __syncthreads();
    int il = tid >> 3;            // 0..31
    int jc = (tid & 7) * 8;       // 0..56
#pragma unroll
    for (int pass = 0; pass < 2; pass++) {
        int row = il + pass * 32;
        uint4 v = *reinterpret_cast<const uint4*>(&tile[row][jc]);
        *reinterpret_cast<uint4*>(&g_maskT[(size_t)(i0 + row) * NN + j0 + jc]) = v;
    }
}

// -------- kernel 2: h = inp@W^T + b (row 0 zeroed); fp16 h + s1 + hsum partials --------
__global__ void __launch_bounds__(256) k_compute_h(const float* __restrict__ inp,
                                                   const float* __restrict__ W_w,
                                                   const float* __restrict__ W_b,
                                                   const float* __restrict__ a) {
    __shared__ __align__(16) float Wsh[64 * 64];
    __shared__ float bsh[64];
    __shared__ float wred[8][64];
    int tid = threadIdx.x, lane = tid & 31, wid = tid >> 5, b = blockIdx.y;
    int n = blockIdx.x * 256 + tid;
    for (int i = tid; i < 64 * 64; i += 256) Wsh[i] = W_w[i];
    if (tid < 64) bsh[tid] = W_b[tid];
    __syncthreads();

    float x[64];
    const float4* src = reinterpret_cast<const float4*>(inp + ((size_t)b * NN + n) * 64);
#pragma unroll
    for (int q = 0; q < 16; q++) {
        float4 v = src[q];
        x[4 * q] = v.x; x[4 * q + 1] = v.y; x[4 * q + 2] = v.z; x[4 * q + 3] = v.w;
    }
    float s1 = 0.f;
    for (int f = 0; f < 64; f++) {
        float acc = bsh[f];
        const float4* wr = reinterpret_cast<const float4*>(Wsh + f * 64);
#pragma unroll
        for (int q = 0; q < 16; q++) {
            float4 w4 = wr[q];
            acc = fmaf(x[4 * q], w4.x, acc);
            acc = fmaf(x[4 * q + 1], w4.y, acc);
            acc = fmaf(x[4 * q + 2], w4.z, acc);
            acc = fmaf(x[4 * q + 3], w4.w, acc);
        }
        if (n == 0) acc = 0.f;
        g_hT[((size_t)b * 64 + f) * NN + n] = __float2half(acc);
        s1 = fmaf(acc, a[(size_t)f * NN + n], s1);
        float v = acc;
#pragma unroll
        for (int off = 16; off > 0; off >>= 1)
            v += __shfl_xor_sync(0xFFFFFFFFu, v, off);
        if (lane == 0) wred[wid][f] = v;
    }
    g_s1[b * NN + n] = s1;
    __syncthreads();
    if (tid < 64) {
        float t = 0.f;
#pragma unroll
        for (int w = 0; w < 8; w++) t += wred[w][tid];
        g_hsumP[blockIdx.x][b][tid] = t;
    }
}

// -------- kernel 2b: finish hsum --------
__global__ void k_hsum_final() {
    int b = threadIdx.x >> 6, f = threadIdx.x & 63;   // 512 threads
    float t = 0.f;
#pragma unroll
    for (int p = 0; p < 16; p++) t += g_hsumP[p][b][f];
    g_hsum[b * 64 + f] = t;
}

// -------- kernel 4: big GEMM (mma.sync fp16, LDSM, 3-stage 1-sync) + s2 epilogue --------
__device__ __forceinline__ void load_chunk(uint32_t stage, const char* Ah,
                                           const char* Bm, int c, int tid) {
    size_t koff = (size_t)c * 128;  // 64 fp16 = 128B per row
#pragma unroll
    for (int p = 0; p < 4; p++) {
        int q = tid + p * 256;                 // 0..1023 = 128 rows x 8 chunks
        int row = q >> 3, cb = (q & 7) * 16;
        uint32_t soff = SW128((uint32_t)(row * 128 + cb));
        size_t goff = (size_t)row * 8192 + koff + cb;
        cp16(stage + soff, Ah + goff);
        cp16(stage + 16384 + soff, Bm + goff);
    }
}

__global__ void __launch_bounds__(256, 2) k_gemm(const float* __restrict__ a) {
    extern __shared__ char smem[];
    uint32_t sb = smem_u32(smem);
    int tid = threadIdx.x, lane = tid & 31, wid = tid >> 5;
    int wm = wid & 3, wn = wid >> 2;          // warp tile: rows wm*32, cols wn*64
    int mtile = blockIdx.x, i0 = blockIdx.y * 128;
    int kslice = blockIdx.z, c0 = kslice * 32;  // 32 chunks of 64 per slice

    const char* Ah = (const char*)g_hT + (size_t)mtile * 128 * 8192;
    const char* Bm = (const char*)g_maskT + (size_t)i0 * 8192;

    float acc[2][8][4];
#pragma unroll
    for (int mt = 0; mt < 2; mt++)
#pragma unroll
        for (int nt = 0; nt < 8; nt++)
#pragma unroll
            for (int r = 0; r < 4; r++) acc[mt][nt][r] = 0.f;

    uint32_t cx = (uint32_t)((lane & 7) << 4);
    uint32_t aoff = (uint32_t)(wm * 32 + (lane & 15)) * 128u;
    uint32_t khA = (uint32_t)(((lane >> 4) & 1) << 4);
    uint32_t boff = 16384u + (uint32_t)(wn * 64 + (lane & 7) + (((lane >> 4) & 1) << 3)) * 128u;
    uint32_t khB = (uint32_t)(((lane >> 3) & 1) << 4);

    // prologue: chunks 0,1
    load_chunk(sb, Ah, Bm, c0, tid);
    CP_COMMIT();
    load_chunk(sb + STAGE_BYTES, Ah, Bm, c0 + 1, tid);
    CP_COMMIT();

    for (int c = 0; c < 32; c++) {
        asm volatile("cp.async.wait_group 1;" ::: "memory");
        __syncthreads();   // chunk c ready; all warps done computing c-1
        if (c + 2 < 32) {
            // buffer (c+2)%3 was computed at c-1; safe to overwrite now
            load_chunk(sb + (uint32_t)((c + 2) % NSTAGE) * STAGE_BYTES, Ah, Bm, c0 + c + 2, tid);
        }
        CP_COMMIT();
        uint32_t so = sb + (uint32_t)(c % NSTAGE) * STAGE_BYTES;
#pragma unroll
        for (int ks = 0; ks < 4; ks++) {
            uint32_t kA = ((uint32_t)(ks * 32) + khA) ^ cx;
            uint32_t kB = ((uint32_t)(ks * 32) + khB) ^ cx;
            uint32_t bfr[8][2];
#pragma unroll
            for (int ntp = 0; ntp < 4; ntp++)
                LDSM4(bfr[2 * ntp][0], bfr[2 * ntp][1], bfr[2 * ntp + 1][0], bfr[2 * ntp + 1][1],
                      so + boff + (uint32_t)ntp * 2048 + kB);
            uint32_t ah[2][4];
#pragma unroll
            for (int mt = 0; mt < 2; mt++)
                LDSM4(ah[mt][0], ah[mt][1], ah[mt][2], ah[mt][3],
                      so + aoff + (uint32_t)mt * 2048 + kA);
#pragma unroll
            for (int mt = 0; mt < 2; mt++)
#pragma unroll
                for (int nt = 0; nt < 8; nt++)
                    mma_f16(acc[mt][nt], ah[mt], bfr[nt]);
        }
    }

    // epilogue: s2p[kslice][b][i] = sum_f C[(b,f)][i] * a2[f][i]
    __syncthreads();
    int tig = lane & 3, grp = lane >> 2;
    float* a2s = (float*)smem;                        // [64][129]
    float* part = (float*)(smem + 64 * 129 * 4);      // [8 warps][64]
    for (int idx = tid; idx < 64 * 128; idx += 256) {
        int f = idx >> 7, cc = idx & 127;
        a2s[f * 129 + cc] = a[(size_t)(64 + f) * NN + i0 + cc];
    }
    __syncthreads();

    float p[8][2];
#pragma unroll
    for (int nt = 0; nt < 8; nt++) { p[nt][0] = 0.f; p[nt][1] = 0.f; }
#pragma unroll
    for (int mt = 0; mt < 2; mt++) {
        int f0 = (wm * 32 + mt * 16 + grp) & 63;
        int f1 = (wm * 32 + mt * 16 + grp + 8) & 63;
#pragma unroll
        for (int nt = 0; nt < 8; nt++) {
            int col = wn * 64 + nt * 8 + tig * 2;
            p[nt][0] += acc[mt][nt][0] * a2s[f0 * 129 + col] +
                        acc[mt][nt][2] * a2s[f1 * 129 + col];
            p[nt][1] += acc[mt][nt][1] * a2s[f0 * 129 + col + 1] +
                        acc[mt][nt][3] * a2s[f1 * 129 + col + 1];
        }
    }
#pragma unroll
    for (int off = 16; off >= 4; off >>= 1)
#pragma unroll
        for (int nt = 0; nt < 8; nt++) {
            p[nt][0] += __shfl_xor_sync(0xFFFFFFFFu, p[nt][0], off);
            p[nt][1] += __shfl_xor_sync(0xFFFFFFFFu, p[nt][1], off);
        }
    if (lane < 4) {
#pragma unroll
        for (int nt = 0; nt < 8; nt++) {
            part[wid * 64 + nt * 8 + tig * 2]     = p[nt][0];
            part[wid * 64 + nt * 8 + tig * 2 + 1] = p[nt][1];
        }
    }
    __syncthreads();
    {
        int bloc = tid >> 7, col = tid & 127;
        int wnn = col >> 6, c64 = col & 63;
        int w0 = wnn * 4 + bloc * 2;   // warps covering this (batch, col-block)
        float v = part[w0 * 64 + c64] + part[(w0 + 1) * 64 + c64];
        g_s2p[kslice][(size_t)(mtile * 2 + bloc) * NN + i0 + col] = v;
    }
}

// -------- kernel 5: out[b,n,f] = leaky(s[b,n] * hsum[b,f]) --------
__global__ void __launch_bounds__(256) k_out(float* __restrict__ out) {
    __shared__ __align__(16) float hs[64];
    int b = blockIdx.y, n0 = blockIdx.x * 16, tid = threadIdx.x;
    if (tid < 64) hs[tid] = g_hsum[b * 64 + tid];
    __syncthreads();
    int r = tid >> 4, q = tid & 15;
    int n = n0 + r;
    float s = (n == 0) ? 0.f
                       : (g_s1[b * NN + n] + g_s2p[0][b * NN + n] + g_s2p[1][b * NN + n]);
    float4 h4 = reinterpret_cast<const float4*>(hs)[q];
    float4 v;
    v.x = s * h4.x; v.y = s * h4.y; v.z = s * h4.z; v.w = s * h4.w;
    v.x = v.x >= 0.f ? v.x : NEG_SLOPE * v.x;
    v.y = v.y >= 0.f ? v.y : NEG_SLOPE * v.y;
    v.z = v.z >= 0.f ? v.z : NEG_SLOPE * v.z;
    v.w = v.w >= 0.f ? v.w : NEG_SLOPE * v.w;
    reinterpret_cast<float4*>(out + ((size_t)b * NN + n) * 64)[q] = v;
}

extern "C" void kernel_launch(void* const* d_in, const int* in_sizes, int n_in,
                              void* d_out, int out_size) {
    const float* inp = (const float*)d_in[0];
    const int*   adj = (const int*)d_in[1];
    const float* W_w = (const float*)d_in[2];
    const float* W_b = (const float*)d_in[3];
    const float* a   = (const float*)d_in[4];
    float* out = (float*)d_out;
    cudaFuncSetAttribute(k_gemm, cudaFuncAttributeMaxDynamicSharedMemorySize, SMEM_DYN);
    k_mask_transpose<<<dim3(64, 64), 256>>>(adj);
    k_compute_h<<<dim3(16, 8), 256>>>(inp, W_w, W_b, a);
    k_hsum_final<<<1, 512>>>();
    k_gemm<<<dim3(4, 32, 2), 256, SMEM_DYN>>>(a);
    k_out<<<dim3(256, 8), 256>>>(out);
}